// round 16
// baseline (speedup 1.0000x reference)
#include <cuda_runtime.h>
#include <cuda_bf16.h>
#include <math.h>
#include <stdint.h>

#define BB 8
#define CC 512
#define PP 1024   // H*W
#define EE 8
#define DH 1024

// Scratch (module-load allocation; none at runtime)
__device__ float g_mean[BB][CC];
__device__ float g_scale[BB][2];
__device__ int   g_expert[BB][2];
__device__ __nv_bfloat16 g_Xbf[BB][CC][PP];        // 8 MB
__device__ __nv_bfloat16 g_W1bf[EE][CC][DH];       // 8 MB
__device__ __nv_bfloat16 g_W2bf[EE][DH][CC];       // 8 MB
__device__ __nv_bfloat16 g_Hbf[BB][2][DH][PP];     // 32 MB

// ---------------------------------------------------------------------------
// helpers
// ---------------------------------------------------------------------------
__device__ __forceinline__ uint32_t smem_u32(const void* p) {
    uint32_t a;
    asm("{ .reg .u64 t; cvta.to.shared.u64 t, %1; cvt.u32.u64 %0, t; }" : "=r"(a) : "l"(p));
    return a;
}
__device__ __forceinline__ void mma_bf16(float* d, const uint32_t* a, const uint32_t* b) {
    asm volatile(
        "mma.sync.aligned.m16n8k16.row.col.f32.bf16.bf16.f32 "
        "{%0,%1,%2,%3}, {%4,%5,%6,%7}, {%8,%9}, {%0,%1,%2,%3};"
        : "+f"(d[0]), "+f"(d[1]), "+f"(d[2]), "+f"(d[3])
        : "r"(a[0]), "r"(a[1]), "r"(a[2]), "r"(a[3]), "r"(b[0]), "r"(b[1]));
}
#define LDSM_X4_T(r0, r1, r2, r3, addr) \
    asm volatile("ldmatrix.sync.aligned.m8n8.x4.trans.shared.b16 {%0,%1,%2,%3}, [%4];" \
        : "=r"(r0), "=r"(r1), "=r"(r2), "=r"(r3) : "r"(addr))
#define CP_ASYNC(dst, src) \
    asm volatile("cp.async.cg.shared.global [%0], [%1], 16;" :: "r"(dst), "l"(src))
#define CP_COMMIT() asm volatile("cp.async.commit_group;" ::: "memory")
#define CP_WAIT1()  asm volatile("cp.async.wait_group 1;" ::: "memory")

// Per-thread loop-invariant LDSM offsets (relative to k32-tile smem base).
// k32 tile = two 4KB k16 subtiles; subtile row = 256B = 16 chunks of 16B,
// chunk' = chunk ^ (k & 7)  — conflict-free for cp.async and ldmatrix.
struct LdsmOff { uint32_t a[4]; uint32_t b[2]; };
__device__ __forceinline__ LdsmOff make_off(int warp_m, int warp_n, int lane) {
    LdsmOff o;
    int kA = (lane & 7) | ((lane & 16) >> 1);
    int mh = (lane & 8) >> 3;
#pragma unroll
    for (int mt = 0; mt < 4; mt++) {
        int chunk = ((warp_m * 64 + mt * 16) >> 3) + mh;
        o.a[mt] = (uint32_t)((kA << 8) + ((chunk ^ (kA & 7)) << 4));
    }
    int kB = (lane & 7) | (lane & 8);
    int nh = (lane & 16) >> 1;
#pragma unroll
    for (int ntp = 0; ntp < 2; ntp++) {
        int chunk = (warp_n * 32 + ntp * 16 + nh) >> 3;
        o.b[ntp] = (uint32_t)((kB << 8) + ((chunk ^ (kB & 7)) << 4));
    }
    return o;
}

// one k16 subtile: 6 LDSM + 16 MMA, addresses = base + hoisted offset
__device__ __forceinline__ void compute_k16(uint32_t sA, uint32_t sB,
                                            const LdsmOff& o, float acc[4][4][4]) {
    uint32_t a[4][4];
#pragma unroll
    for (int mt = 0; mt < 4; mt++)
        LDSM_X4_T(a[mt][0], a[mt][1], a[mt][2], a[mt][3], sA + o.a[mt]);
    uint32_t bfr[2][4];
#pragma unroll
    for (int ntp = 0; ntp < 2; ntp++)
        LDSM_X4_T(bfr[ntp][0], bfr[ntp][1], bfr[ntp][2], bfr[ntp][3], sB + o.b[ntp]);
#pragma unroll
    for (int mt = 0; mt < 4; mt++)
#pragma unroll
        for (int nt = 0; nt < 4; nt++)
            mma_bf16(acc[mt][nt], a[mt], &bfr[nt >> 1][(nt & 1) << 1]);
}

// cp.async one k32 tile; pA/pB already carry the per-thread offset (k*ld + j*8)
__device__ __forceinline__ void cp_k32(uint32_t dstA, uint32_t dstB, uint32_t off,
                                       const __nv_bfloat16* pA, int ldA,
                                       const __nv_bfloat16* pB, int ldB) {
    CP_ASYNC(dstA + off, pA);
    CP_ASYNC(dstB + off, pB);
    CP_ASYNC(dstA + off + 4096, pA + (size_t)16 * ldA);
    CP_ASYNC(dstB + off + 4096, pB + (size_t)16 * ldB);
}

// ---------------------------------------------------------------------------
// Kernel 0: W1 + W2 f32 -> bf16 in one launch
// ---------------------------------------------------------------------------
__global__ void f2bf_kernel(const float4* __restrict__ in1, const float4* __restrict__ in2,
                            uint2* __restrict__ out1, uint2* __restrict__ out2, int n4) {
    int i = blockIdx.x * blockDim.x + threadIdx.x;
    const float4* src; uint2* dst; int idx;
    if (i < n4)      { src = in1; dst = out1; idx = i; }
    else             { src = in2; dst = out2; idx = i - n4; if (idx >= n4) return; }
    float4 v = src[idx];
    __nv_bfloat162 lo = __floats2bfloat162_rn(v.x, v.y);
    __nv_bfloat162 hi = __floats2bfloat162_rn(v.z, v.w);
    dst[idx] = make_uint2(*(uint32_t*)&lo, *(uint32_t*)&hi);
}

// ---------------------------------------------------------------------------
// Kernel 1: per-(b,c) spatial mean + X -> bf16 conversion (same read)
// ---------------------------------------------------------------------------
__global__ void mean_kernel(const float* __restrict__ x) {
    int bc = blockIdx.x;
    const float4* p = (const float4*)(x + (size_t)bc * PP);
    float4 v = p[threadIdx.x];
    __nv_bfloat162 lo = __floats2bfloat162_rn(v.x, v.y);
    __nv_bfloat162 hi = __floats2bfloat162_rn(v.z, v.w);
    uint2* xb = (uint2*)(&g_Xbf[0][0][0] + (size_t)bc * PP);
    xb[threadIdx.x] = make_uint2(*(uint32_t*)&lo, *(uint32_t*)&hi);

    float s = v.x + v.y + v.z + v.w;
#pragma unroll
    for (int o = 16; o; o >>= 1) s += __shfl_down_sync(0xffffffffu, s, o);
    __shared__ float ws[8];
    if ((threadIdx.x & 31) == 0) ws[threadIdx.x >> 5] = s;
    __syncthreads();
    if (threadIdx.x == 0) {
        float t = 0.f;
#pragma unroll
        for (int i = 0; i < 8; i++) t += ws[i];
        g_mean[bc >> 9][bc & 511] = t * (1.0f / PP);
    }
}

// ---------------------------------------------------------------------------
// Kernel 2: gate
// ---------------------------------------------------------------------------
__global__ void gate_kernel(const float* __restrict__ Wg, const float* __restrict__ bg,
                            const float* __restrict__ kk) {
    __shared__ float sl[BB][EE];
    int t = threadIdx.x;
    int w = t >> 5, lane = t & 31;
#pragma unroll
    for (int q = 0; q < 4; q++) {
        int pe = w * 4 + q;
        int b = pe >> 3, e = pe & 7;
        float acc = 0.f;
        for (int c = lane; c < CC; c += 32)
            acc = fmaf(g_mean[b][c], Wg[c * EE + e], acc);
#pragma unroll
        for (int o = 16; o; o >>= 1) acc += __shfl_down_sync(0xffffffffu, acc, o);
        if (lane == 0) sl[b][e] = acc + bg[e];
    }
    __syncthreads();
    if (t < BB) {
        int b = t;
        float m = -1e30f;
#pragma unroll
        for (int e = 0; e < EE; e++) m = fmaxf(m, sl[b][e]);
        float wv[EE]; float sum = 0.f;
#pragma unroll
        for (int e = 0; e < EE; e++) { wv[e] = expf(sl[b][e] - m); sum += wv[e]; }
        float inv = 1.0f / sum;
#pragma unroll
        for (int e = 0; e < EE; e++) wv[e] *= inv;
        int i0 = 0;
#pragma unroll
        for (int e = 1; e < EE; e++) if (wv[e] > wv[i0]) i0 = e;
        int i1 = (i0 == 0) ? 1 : 0;
#pragma unroll
        for (int e = 0; e < EE; e++) { if (e == i0 || e == i1) continue; if (wv[e] > wv[i1]) i1 = e; }
        float kb = kk[b];
        g_expert[b][0] = i0; g_expert[b][1] = i1;
        g_scale[b][0]  = wv[i0] * kb; g_scale[b][1] = wv[i1] * kb;
    }
}

// ---------------------------------------------------------------------------
// Kernel 3: GEMM1  H[d,p] = s * gelu(sum_c W1[e][c][d] X[b][c][p] + b1[e][d])
// ---------------------------------------------------------------------------
__global__ __launch_bounds__(256, 2)
void gemm1_mma(const float* __restrict__ b1v) {
    __shared__ __align__(256) char smA[3][8192];
    __shared__ __align__(256) char smB[3][8192];

    const int tid = threadIdx.x;
    const int wid = tid >> 5, lane = tid & 31;
    const LdsmOff off = make_off(wid >> 2, wid & 3, lane);

    const int pair = blockIdx.y;
    const int b = pair >> 1, slot = pair & 1;
    const int e = g_expert[b][slot];
    const float s = g_scale[b][slot];
    const int td = (blockIdx.x >> 3) << 7;
    const int tp = (blockIdx.x & 7) << 7;

    // per-thread cp.async source pointers / dst offset
    const int ck = tid >> 4;           // 0..15
    const int cj = tid & 15;           // 0..15
    const uint32_t coff = (uint32_t)((ck << 8) + ((cj ^ (ck & 7)) << 4));
    const __nv_bfloat16* pA = &g_W1bf[e][0][0] + td + (size_t)ck * DH + cj * 8;
    const __nv_bfloat16* pB = &g_Xbf[b][0][0] + tp + (size_t)ck * PP + cj * 8;

    uint32_t sa[3], sb[3];
#pragma unroll
    for (int i = 0; i < 3; i++) { sa[i] = smem_u32(smA[i]); sb[i] = smem_u32(smB[i]); }

    const int KT = CC / 32;   // 16
    cp_k32(sa[0], sb[0], coff, pA, DH, pB, PP); CP_COMMIT();
    pA += (size_t)32 * DH; pB += (size_t)32 * PP;
    cp_k32(sa[1], sb[1], coff, pA, DH, pB, PP); CP_COMMIT();
    pA += (size_t)32 * DH; pB += (size_t)32 * PP;

    float acc[4][4][4];
#pragma unroll
    for (int i = 0; i < 4; i++)
#pragma unroll
        for (int j = 0; j < 4; j++)
#pragma unroll
            for (int q = 0; q < 4; q++) acc[i][j][q] = 0.f;

    int st = 0, pf = 2;
#pragma unroll 1
    for (int kt = 0; kt < KT; kt++) {
        CP_WAIT1();
        __syncthreads();
        if (kt + 2 < KT) {
            cp_k32(sa[pf], sb[pf], coff, pA, DH, pB, PP);
            pA += (size_t)32 * DH; pB += (size_t)32 * PP;
        }
        CP_COMMIT();
        compute_k16(sa[st], sb[st], off, acc);
        compute_k16(sa[st] + 4096, sb[st] + 4096, off, acc);
        __syncthreads();
        if (++st == 3) st = 0;
        if (++pf == 3) pf = 0;
    }

    // epilogue: bias + exact gelu + scale -> g_Hbf (bf16)
    const int warp_m = wid >> 2, warp_n = wid & 3;
    const int mrow = lane >> 2;
    const int ncol = (lane & 3) << 1;
    __nv_bfloat16* Hbase = &g_Hbf[b][slot][0][0];
#pragma unroll
    for (int mt = 0; mt < 4; mt++) {
#pragma unroll
        for (int h = 0; h < 2; h++) {
            int d = td + warp_m * 64 + mt * 16 + mrow + h * 8;
            float bias = b1v[e * DH + d];
            __nv_bfloat16* Hrow = Hbase + (size_t)d * PP + tp + warp_n * 32;
#pragma unroll
            for (int nt = 0; nt < 4; nt++) {
                float x0 = acc[mt][nt][h * 2 + 0] + bias;
                float x1 = acc[mt][nt][h * 2 + 1] + bias;
                float o0 = s * (0.5f * x0 * (1.0f + erff(x0 * 0.70710678118654752f)));
                float o1 = s * (0.5f * x1 * (1.0f + erff(x1 * 0.70710678118654752f)));
                __nv_bfloat162 pk = __floats2bfloat162_rn(o0, o1);
                *(uint32_t*)(Hrow + nt * 8 + ncol) = *(uint32_t*)&pk;
            }
        }
    }
}

// ---------------------------------------------------------------------------
// Kernel 4: GEMM2  out = X + (s0 b2[e0] + s1 b2[e1]) + sum_slot W2[e]^T H
// ---------------------------------------------------------------------------
__global__ __launch_bounds__(256, 2)
void gemm2_mma(const float* __restrict__ X, const float* __restrict__ b2,
               float* __restrict__ out) {
    __shared__ __align__(256) char smA[3][8192];
    __shared__ __align__(256) char smB[3][8192];

    const int tid = threadIdx.x;
    const int wid = tid >> 5, lane = tid & 31;
    const LdsmOff off = make_off(wid >> 2, wid & 3, lane);

    const int b = blockIdx.y;
    const int tc = (blockIdx.x >> 3) << 7;
    const int tp = (blockIdx.x & 7) << 7;
    const int e0 = g_expert[b][0], e1 = g_expert[b][1];
    const float s0 = g_scale[b][0], s1 = g_scale[b][1];

    const int ck = tid >> 4;
    const int cj = tid & 15;
    const uint32_t coff = (uint32_t)((ck << 8) + ((cj ^ (ck & 7)) << 4));
    const size_t tbA = (size_t)ck * CC + cj * 8;
    const size_t tbB = (size_t)ck * PP + cj * 8;
    const __nv_bfloat16* pA = &g_W2bf[e0][0][0] + tc + tbA;
    const __nv_bfloat16* pB = &g_Hbf[b][0][0][0] + tp + tbB;
    const __nv_bfloat16* A1 = &g_W2bf[e1][0][0] + tc + tbA;
    const __nv_bfloat16* H1 = &g_Hbf[b][1][0][0] + tp + tbB;

    uint32_t sa[3], sb[3];
#pragma unroll
    for (int i = 0; i < 3; i++) { sa[i] = smem_u32(smA[i]); sb[i] = smem_u32(smB[i]); }

    const int KT = 2 * DH / 32;   // 64
    cp_k32(sa[0], sb[0], coff, pA, CC, pB, PP); CP_COMMIT();
    pA += (size_t)32 * CC; pB += (size_t)32 * PP;
    cp_k32(sa[1], sb[1], coff, pA, CC, pB, PP); CP_COMMIT();
    pA += (size_t)32 * CC; pB += (size_t)32 * PP;

    float acc[4][4][4];
#pragma unroll
    for (int i = 0; i < 4; i++)
#pragma unroll
        for (int j = 0; j < 4; j++)
#pragma unroll
            for (int q = 0; q < 4; q++) acc[i][j][q] = 0.f;

    int st = 0, pf = 2;
#pragma unroll 1
    for (int kt = 0; kt < KT; kt++) {
        CP_WAIT1();
        __syncthreads();
        if (kt + 2 < KT) {
            if (kt + 2 == 32) { pA = A1; pB = H1; }   // slot switch
            cp_k32(sa[pf], sb[pf], coff, pA, CC, pB, PP);
            pA += (size_t)32 * CC; pB += (size_t)32 * PP;
        }
        CP_COMMIT();
        compute_k16(sa[st], sb[st], off, acc);
        compute_k16(sa[st] + 4096, sb[st] + 4096, off, acc);
        __syncthreads();
        if (++st == 3) st = 0;
        if (++pf == 3) pf = 0;
    }

    // epilogue: residual (fp32) + combined b2 bias inline
    const int warp_m = wid >> 2, warp_n = wid & 3;
    const int mrow = lane >> 2;
    const int ncol = (lane & 3) << 1;
#pragma unroll
    for (int mt = 0; mt < 4; mt++) {
#pragma unroll
        for (int h = 0; h < 2; h++) {
            int c = tc + warp_m * 64 + mt * 16 + mrow + h * 8;
            float cb = s0 * b2[e0 * CC + c] + s1 * b2[e1 * CC + c];
            size_t rowbase = ((size_t)(b * CC + c)) * PP + tp + warp_n * 32;
#pragma unroll
            for (int nt = 0; nt < 4; nt++) {
                float2 xin = *(const float2*)(X + rowbase + nt * 8 + ncol);
                float2 o;
                o.x = xin.x + cb + acc[mt][nt][h * 2 + 0];
                o.y = xin.y + cb + acc[mt][nt][h * 2 + 1];
                *(float2*)(out + rowbase + nt * 8 + ncol) = o;
            }
        }
    }
}

// ---------------------------------------------------------------------------
extern "C" void kernel_launch(void* const* d_in, const int* in_sizes, int n_in,
                              void* d_out, int out_size) {
    const float* inputs = (const float*)d_in[0];
    const float* kk     = (const float*)d_in[1];
    const float* Wg     = (const float*)d_in[2];
    const float* bg     = (const float*)d_in[3];
    const float* W1     = (const float*)d_in[4];
    const float* b1     = (const float*)d_in[5];
    const float* W2     = (const float*)d_in[6];
    const float* b2     = (const float*)d_in[7];
    float* out = (float*)d_out;

    __nv_bfloat16 *w1bf_p, *w2bf_p;
    cudaGetSymbolAddress((void**)&w1bf_p, g_W1bf);
    cudaGetSymbolAddress((void**)&w2bf_p, g_W2bf);

    const int n4 = EE * CC * DH / 4;
    f2bf_kernel<<<(2 * n4 + 255) / 256, 256>>>((const float4*)W1, (const float4*)W2,
                                               (uint2*)w1bf_p, (uint2*)w2bf_p, n4);
    mean_kernel<<<BB * CC, 256>>>(inputs);
    gate_kernel<<<1, 512>>>(Wg, bg, kk);
    gemm1_mma<<<dim3(64, 16), 256>>>(b1);
    gemm2_mma<<<dim3(32, 8), 256>>>(inputs, b2, out);
}

// round 17
// speedup vs baseline: 1.0170x; 1.0170x over previous
#include <cuda_runtime.h>
#include <cuda_bf16.h>
#include <math.h>
#include <stdint.h>

#define BB 8
#define CC 512
#define PP 1024   // H*W
#define EE 8
#define DH 1024

// Scratch (module-load allocation; none at runtime)
__device__ float g_mean[BB][CC];
__device__ float g_scale[BB][2];
__device__ int   g_expert[BB][2];
__device__ __nv_bfloat16 g_Xbf[BB][CC][PP];        // 8 MB
__device__ __nv_bfloat16 g_W1bf[EE][CC][DH];       // 8 MB
__device__ __nv_bfloat16 g_W2bf[EE][DH][CC];       // 8 MB
__device__ __nv_bfloat16 g_Hbf[BB][2][DH][PP];     // 32 MB

// ---------------------------------------------------------------------------
// helpers
// ---------------------------------------------------------------------------
__device__ __forceinline__ uint32_t smem_u32(const void* p) {
    uint32_t a;
    asm("{ .reg .u64 t; cvta.to.shared.u64 t, %1; cvt.u32.u64 %0, t; }" : "=r"(a) : "l"(p));
    return a;
}
__device__ __forceinline__ void mma_bf16(float* d, const uint32_t* a, const uint32_t* b) {
    asm volatile(
        "mma.sync.aligned.m16n8k16.row.col.f32.bf16.bf16.f32 "
        "{%0,%1,%2,%3}, {%4,%5,%6,%7}, {%8,%9}, {%0,%1,%2,%3};"
        : "+f"(d[0]), "+f"(d[1]), "+f"(d[2]), "+f"(d[3])
        : "r"(a[0]), "r"(a[1]), "r"(a[2]), "r"(a[3]), "r"(b[0]), "r"(b[1]));
}
#define LDSM_X4_T(r0, r1, r2, r3, addr) \
    asm volatile("ldmatrix.sync.aligned.m8n8.x4.trans.shared.b16 {%0,%1,%2,%3}, [%4];" \
        : "=r"(r0), "=r"(r1), "=r"(r2), "=r"(r3) : "r"(addr))
#define CP_ASYNC(dst, src) \
    asm volatile("cp.async.cg.shared.global [%0], [%1], 16;" :: "r"(dst), "l"(src))
#define CP_COMMIT() asm volatile("cp.async.commit_group;" ::: "memory")
#define CP_WAIT1()  asm volatile("cp.async.wait_group 1;" ::: "memory")

// Per-thread loop-invariant LDSM offsets (relative to k32-tile smem base).
// k32 tile = two 4KB k16 subtiles; subtile row = 256B = 16 chunks of 16B,
// chunk' = chunk ^ (k & 7)  — conflict-free for cp.async and ldmatrix.
struct LdsmOff { uint32_t a[4]; uint32_t b[2]; };
__device__ __forceinline__ LdsmOff make_off(int warp_m, int warp_n, int lane) {
    LdsmOff o;
    int kA = (lane & 7) | ((lane & 16) >> 1);
    int mh = (lane & 8) >> 3;
#pragma unroll
    for (int mt = 0; mt < 4; mt++) {
        int chunk = ((warp_m * 64 + mt * 16) >> 3) + mh;
        o.a[mt] = (uint32_t)((kA << 8) + ((chunk ^ (kA & 7)) << 4));
    }
    int kB = (lane & 7) | (lane & 8);
    int nh = (lane & 16) >> 1;
#pragma unroll
    for (int ntp = 0; ntp < 2; ntp++) {
        int chunk = (warp_n * 32 + ntp * 16 + nh) >> 3;
        o.b[ntp] = (uint32_t)((kB << 8) + ((chunk ^ (kB & 7)) << 4));
    }
    return o;
}

// one k16 subtile: 6 LDSM + 16 MMA, addresses = base + hoisted offset
__device__ __forceinline__ void compute_k16(uint32_t sA, uint32_t sB,
                                            const LdsmOff& o, float acc[4][4][4]) {
    uint32_t a[4][4];
#pragma unroll
    for (int mt = 0; mt < 4; mt++)
        LDSM_X4_T(a[mt][0], a[mt][1], a[mt][2], a[mt][3], sA + o.a[mt]);
    uint32_t bfr[2][4];
#pragma unroll
    for (int ntp = 0; ntp < 2; ntp++)
        LDSM_X4_T(bfr[ntp][0], bfr[ntp][1], bfr[ntp][2], bfr[ntp][3], sB + o.b[ntp]);
#pragma unroll
    for (int mt = 0; mt < 4; mt++)
#pragma unroll
        for (int nt = 0; nt < 4; nt++)
            mma_bf16(acc[mt][nt], a[mt], &bfr[nt >> 1][(nt & 1) << 1]);
}

// cp.async one k32 tile; pA/pB already carry the per-thread offset (k*ld + j*8)
__device__ __forceinline__ void cp_k32(uint32_t dstA, uint32_t dstB, uint32_t off,
                                       const __nv_bfloat16* pA, int ldA,
                                       const __nv_bfloat16* pB, int ldB) {
    CP_ASYNC(dstA + off, pA);
    CP_ASYNC(dstB + off, pB);
    CP_ASYNC(dstA + off + 4096, pA + (size_t)16 * ldA);
    CP_ASYNC(dstB + off + 4096, pB + (size_t)16 * ldB);
}

// ---------------------------------------------------------------------------
// Kernel 0: W1 + W2 f32 -> bf16 in one launch
// ---------------------------------------------------------------------------
__global__ void f2bf_kernel(const float4* __restrict__ in1, const float4* __restrict__ in2,
                            uint2* __restrict__ out1, uint2* __restrict__ out2, int n4) {
    int i = blockIdx.x * blockDim.x + threadIdx.x;
    const float4* src; uint2* dst; int idx;
    if (i < n4)      { src = in1; dst = out1; idx = i; }
    else             { src = in2; dst = out2; idx = i - n4; if (idx >= n4) return; }
    float4 v = src[idx];
    __nv_bfloat162 lo = __floats2bfloat162_rn(v.x, v.y);
    __nv_bfloat162 hi = __floats2bfloat162_rn(v.z, v.w);
    dst[idx] = make_uint2(*(uint32_t*)&lo, *(uint32_t*)&hi);
}

// ---------------------------------------------------------------------------
// Kernel 1: per-(b,c) spatial mean + X -> bf16 conversion (same read)
// ---------------------------------------------------------------------------
__global__ void mean_kernel(const float* __restrict__ x) {
    int bc = blockIdx.x;
    const float4* p = (const float4*)(x + (size_t)bc * PP);
    float4 v = p[threadIdx.x];
    __nv_bfloat162 lo = __floats2bfloat162_rn(v.x, v.y);
    __nv_bfloat162 hi = __floats2bfloat162_rn(v.z, v.w);
    uint2* xb = (uint2*)(&g_Xbf[0][0][0] + (size_t)bc * PP);
    xb[threadIdx.x] = make_uint2(*(uint32_t*)&lo, *(uint32_t*)&hi);

    float s = v.x + v.y + v.z + v.w;
#pragma unroll
    for (int o = 16; o; o >>= 1) s += __shfl_down_sync(0xffffffffu, s, o);
    __shared__ float ws[8];
    if ((threadIdx.x & 31) == 0) ws[threadIdx.x >> 5] = s;
    __syncthreads();
    if (threadIdx.x == 0) {
        float t = 0.f;
#pragma unroll
        for (int i = 0; i < 8; i++) t += ws[i];
        g_mean[bc >> 9][bc & 511] = t * (1.0f / PP);
    }
}

// ---------------------------------------------------------------------------
// Kernel 2: gate
// ---------------------------------------------------------------------------
__global__ void gate_kernel(const float* __restrict__ Wg, const float* __restrict__ bg,
                            const float* __restrict__ kk) {
    __shared__ float sl[BB][EE];
    int t = threadIdx.x;
    int w = t >> 5, lane = t & 31;
#pragma unroll
    for (int q = 0; q < 4; q++) {
        int pe = w * 4 + q;
        int b = pe >> 3, e = pe & 7;
        float acc = 0.f;
        for (int c = lane; c < CC; c += 32)
            acc = fmaf(g_mean[b][c], Wg[c * EE + e], acc);
#pragma unroll
        for (int o = 16; o; o >>= 1) acc += __shfl_down_sync(0xffffffffu, acc, o);
        if (lane == 0) sl[b][e] = acc + bg[e];
    }
    __syncthreads();
    if (t < BB) {
        int b = t;
        float m = -1e30f;
#pragma unroll
        for (int e = 0; e < EE; e++) m = fmaxf(m, sl[b][e]);
        float wv[EE]; float sum = 0.f;
#pragma unroll
        for (int e = 0; e < EE; e++) { wv[e] = expf(sl[b][e] - m); sum += wv[e]; }
        float inv = 1.0f / sum;
#pragma unroll
        for (int e = 0; e < EE; e++) wv[e] *= inv;
        int i0 = 0;
#pragma unroll
        for (int e = 1; e < EE; e++) if (wv[e] > wv[i0]) i0 = e;
        int i1 = (i0 == 0) ? 1 : 0;
#pragma unroll
        for (int e = 0; e < EE; e++) { if (e == i0 || e == i1) continue; if (wv[e] > wv[i1]) i1 = e; }
        float kb = kk[b];
        g_expert[b][0] = i0; g_expert[b][1] = i1;
        g_scale[b][0]  = wv[i0] * kb; g_scale[b][1] = wv[i1] * kb;
    }
}

// ---------------------------------------------------------------------------
// Kernel 3: GEMM1  H[d,p] = s * gelu(sum_c W1[e][c][d] X[b][c][p] + b1[e][d])
// ---------------------------------------------------------------------------
__global__ __launch_bounds__(256, 2)
void gemm1_mma(const float* __restrict__ b1v) {
    __shared__ __align__(256) char smA[3][8192];
    __shared__ __align__(256) char smB[3][8192];

    const int tid = threadIdx.x;
    const int wid = tid >> 5, lane = tid & 31;
    const LdsmOff off = make_off(wid >> 2, wid & 3, lane);

    const int pair = blockIdx.y;
    const int b = pair >> 1, slot = pair & 1;
    const int e = g_expert[b][slot];
    const float s = g_scale[b][slot];
    const int td = (blockIdx.x >> 3) << 7;
    const int tp = (blockIdx.x & 7) << 7;

    // per-thread cp.async source pointers / dst offset
    const int ck = tid >> 4;           // 0..15
    const int cj = tid & 15;           // 0..15
    const uint32_t coff = (uint32_t)((ck << 8) + ((cj ^ (ck & 7)) << 4));
    const __nv_bfloat16* pA = &g_W1bf[e][0][0] + td + (size_t)ck * DH + cj * 8;
    const __nv_bfloat16* pB = &g_Xbf[b][0][0] + tp + (size_t)ck * PP + cj * 8;

    uint32_t sa[3], sb[3];
#pragma unroll
    for (int i = 0; i < 3; i++) { sa[i] = smem_u32(smA[i]); sb[i] = smem_u32(smB[i]); }

    const int KT = CC / 32;   // 16
    cp_k32(sa[0], sb[0], coff, pA, DH, pB, PP); CP_COMMIT();
    pA += (size_t)32 * DH; pB += (size_t)32 * PP;
    cp_k32(sa[1], sb[1], coff, pA, DH, pB, PP); CP_COMMIT();
    pA += (size_t)32 * DH; pB += (size_t)32 * PP;

    float acc[4][4][4];
#pragma unroll
    for (int i = 0; i < 4; i++)
#pragma unroll
        for (int j = 0; j < 4; j++)
#pragma unroll
            for (int q = 0; q < 4; q++) acc[i][j][q] = 0.f;

    int st = 0, pf = 2;
#pragma unroll 1
    for (int kt = 0; kt < KT; kt++) {
        CP_WAIT1();
        __syncthreads();
        if (kt + 2 < KT) {
            cp_k32(sa[pf], sb[pf], coff, pA, DH, pB, PP);
            pA += (size_t)32 * DH; pB += (size_t)32 * PP;
        }
        CP_COMMIT();
        compute_k16(sa[st], sb[st], off, acc);
        compute_k16(sa[st] + 4096, sb[st] + 4096, off, acc);
        __syncthreads();
        if (++st == 3) st = 0;
        if (++pf == 3) pf = 0;
    }

    // epilogue: bias + exact gelu + scale -> g_Hbf (bf16)
    const int warp_m = wid >> 2, warp_n = wid & 3;
    const int mrow = lane >> 2;
    const int ncol = (lane & 3) << 1;
    __nv_bfloat16* Hbase = &g_Hbf[b][slot][0][0];
#pragma unroll
    for (int mt = 0; mt < 4; mt++) {
#pragma unroll
        for (int h = 0; h < 2; h++) {
            int d = td + warp_m * 64 + mt * 16 + mrow + h * 8;
            float bias = b1v[e * DH + d];
            __nv_bfloat16* Hrow = Hbase + (size_t)d * PP + tp + warp_n * 32;
#pragma unroll
            for (int nt = 0; nt < 4; nt++) {
                float x0 = acc[mt][nt][h * 2 + 0] + bias;
                float x1 = acc[mt][nt][h * 2 + 1] + bias;
                float o0 = s * (0.5f * x0 * (1.0f + erff(x0 * 0.70710678118654752f)));
                float o1 = s * (0.5f * x1 * (1.0f + erff(x1 * 0.70710678118654752f)));
                __nv_bfloat162 pk = __floats2bfloat162_rn(o0, o1);
                *(uint32_t*)(Hrow + nt * 8 + ncol) = *(uint32_t*)&pk;
            }
        }
    }
}

// ---------------------------------------------------------------------------
// Kernel 4: GEMM2  out = X + (s0 b2[e0] + s1 b2[e1]) + sum_slot W2[e]^T H
// ---------------------------------------------------------------------------
__global__ __launch_bounds__(256, 2)
void gemm2_mma(const float* __restrict__ X, const float* __restrict__ b2,
               float* __restrict__ out) {
    __shared__ __align__(256) char smA[3][8192];
    __shared__ __align__(256) char smB[3][8192];

    const int tid = threadIdx.x;
    const int wid = tid >> 5, lane = tid & 31;
    const LdsmOff off = make_off(wid >> 2, wid & 3, lane);

    const int b = blockIdx.y;
    const int tc = (blockIdx.x >> 3) << 7;
    const int tp = (blockIdx.x & 7) << 7;
    const int e0 = g_expert[b][0], e1 = g_expert[b][1];
    const float s0 = g_scale[b][0], s1 = g_scale[b][1];

    const int ck = tid >> 4;
    const int cj = tid & 15;
    const uint32_t coff = (uint32_t)((ck << 8) + ((cj ^ (ck & 7)) << 4));
    const size_t tbA = (size_t)ck * CC + cj * 8;
    const size_t tbB = (size_t)ck * PP + cj * 8;
    const __nv_bfloat16* pA = &g_W2bf[e0][0][0] + tc + tbA;
    const __nv_bfloat16* pB = &g_Hbf[b][0][0][0] + tp + tbB;
    const __nv_bfloat16* A1 = &g_W2bf[e1][0][0] + tc + tbA;
    const __nv_bfloat16* H1 = &g_Hbf[b][1][0][0] + tp + tbB;

    uint32_t sa[3], sb[3];
#pragma unroll
    for (int i = 0; i < 3; i++) { sa[i] = smem_u32(smA[i]); sb[i] = smem_u32(smB[i]); }

    const int KT = 2 * DH / 32;   // 64
    cp_k32(sa[0], sb[0], coff, pA, CC, pB, PP); CP_COMMIT();
    pA += (size_t)32 * CC; pB += (size_t)32 * PP;
    cp_k32(sa[1], sb[1], coff, pA, CC, pB, PP); CP_COMMIT();
    pA += (size_t)32 * CC; pB += (size_t)32 * PP;

    float acc[4][4][4];
#pragma unroll
    for (int i = 0; i < 4; i++)
#pragma unroll
        for (int j = 0; j < 4; j++)
#pragma unroll
            for (int q = 0; q < 4; q++) acc[i][j][q] = 0.f;

    int st = 0, pf = 2;
#pragma unroll 1
    for (int kt = 0; kt < KT; kt++) {
        CP_WAIT1();
        __syncthreads();
        if (kt + 2 < KT) {
            if (kt + 2 == 32) { pA = A1; pB = H1; }   // slot switch
            cp_k32(sa[pf], sb[pf], coff, pA, CC, pB, PP);
            pA += (size_t)32 * CC; pB += (size_t)32 * PP;
        }
        CP_COMMIT();
        compute_k16(sa[st], sb[st], off, acc);
        compute_k16(sa[st] + 4096, sb[st] + 4096, off, acc);
        __syncthreads();
        if (++st == 3) st = 0;
        if (++pf == 3) pf = 0;
    }

    // epilogue: residual (fp32) + combined b2 bias inline
    const int warp_m = wid >> 2, warp_n = wid & 3;
    const int mrow = lane >> 2;
    const int ncol = (lane & 3) << 1;
#pragma unroll
    for (int mt = 0; mt < 4; mt++) {
#pragma unroll
        for (int h = 0; h < 2; h++) {
            int c = tc + warp_m * 64 + mt * 16 + mrow + h * 8;
            float cb = s0 * b2[e0 * CC + c] + s1 * b2[e1 * CC + c];
            size_t rowbase = ((size_t)(b * CC + c)) * PP + tp + warp_n * 32;
#pragma unroll
            for (int nt = 0; nt < 4; nt++) {
                float2 xin = *(const float2*)(X + rowbase + nt * 8 + ncol);
                float2 o;
                o.x = xin.x + cb + acc[mt][nt][h * 2 + 0];
                o.y = xin.y + cb + acc[mt][nt][h * 2 + 1];
                *(float2*)(out + rowbase + nt * 8 + ncol) = o;
            }
        }
    }
}

// ---------------------------------------------------------------------------
extern "C" void kernel_launch(void* const* d_in, const int* in_sizes, int n_in,
                              void* d_out, int out_size) {
    const float* inputs = (const float*)d_in[0];
    const float* kk     = (const float*)d_in[1];
    const float* Wg     = (const float*)d_in[2];
    const float* bg     = (const float*)d_in[3];
    const float* W1     = (const float*)d_in[4];
    const float* b1     = (const float*)d_in[5];
    const float* W2     = (const float*)d_in[6];
    const float* b2     = (const float*)d_in[7];
    float* out = (float*)d_out;

    __nv_bfloat16 *w1bf_p, *w2bf_p;
    cudaGetSymbolAddress((void**)&w1bf_p, g_W1bf);
    cudaGetSymbolAddress((void**)&w2bf_p, g_W2bf);

    const int n4 = EE * CC * DH / 4;
    f2bf_kernel<<<(2 * n4 + 255) / 256, 256>>>((const float4*)W1, (const float4*)W2,
                                               (uint2*)w1bf_p, (uint2*)w2bf_p, n4);
    mean_kernel<<<BB * CC, 256>>>(inputs);
    gate_kernel<<<1, 512>>>(Wg, bg, kk);
    gemm1_mma<<<dim3(64, 16), 256>>>(b1);
    gemm2_mma<<<dim3(32, 8), 256>>>(inputs, b2, out);
}